// round 1
// baseline (speedup 1.0000x reference)
#include <cuda_runtime.h>

#define NB 2
#define NN 2048
#define FIN 128
#define FE 64
#define BN2 (NB*NN*NN)                 // 8388608
#define OFF_ROWS 262144
#define OFF_WGT  (262144 + 2*BN2)      // 17039360

__device__ float g_xw[NB*NN*FE];       // x @ W
__device__ float g_part[2*NB*NN*FE];   // k-split partials of A@xw
__device__ float g_cent[NB*FE];
__device__ float g_usq[NB*NN];         // unscaled sum((x-c)^2) per row
__device__ unsigned int g_maxbits;     // max |x-c| as float bits

// ---------------- K0: xw = x @ W  (tiny GEMM, W resident in smem) ------------
__global__ void k0_xw(const float* __restrict__ x, const float* __restrict__ W) {
    __shared__ float Wsh[FIN*FE];      // 32 KB
    __shared__ float xsh[4][FIN];
    int tid = threadIdx.x;             // 256
    for (int i = tid; i < FIN*FE; i += 256) Wsh[i] = W[i];
    int rowBase = blockIdx.x * 16;
    int rloc = tid >> 6, e = tid & 63;
    for (int pass = 0; pass < 4; ++pass) {
        __syncthreads();
        int r0 = rowBase + pass * 4;
        for (int i = tid; i < 4*FIN; i += 256)
            xsh[i >> 7][i & 127] = x[(size_t)r0*FIN + i];
        __syncthreads();
        float acc = 0.f;
        #pragma unroll
        for (int k = 0; k < FIN; ++k)
            acc = fmaf(xsh[rloc][k], Wsh[k*FE + e], acc);
        g_xw[(size_t)(r0 + rloc)*FE + e] = acc;
    }
}

// ---------------- K1: partial = A @ xw  (BM=64, BN=64, BK=32, ksplit=2) ------
__global__ void k1_gemm(const float* __restrict__ A) {
    __shared__ float Ast[32][68];      // [k][row], transposed for LDS.128
    __shared__ float Xs[32][68];       // [k][e]
    int b = blockIdx.z, ks = blockIdx.y;
    int i0 = blockIdx.x * 64;
    int tid = threadIdx.x;
    int ty = tid >> 4, tx = tid & 15;
    const float* Ab = A + (size_t)b*NN*NN;
    const float* Xb = g_xw + (size_t)b*NN*FE;
    float acc[4][4] = {};
    int kbeg = ks * (NN/2), kend = kbeg + NN/2;
    for (int k0 = kbeg; k0 < kend; k0 += 32) {
        {   // A tile 64 rows x 32 k -> transposed
            int r = tid >> 2;
            int kq = (tid & 3) * 4;
            #pragma unroll
            for (int half = 0; half < 2; ++half) {
                int kk = kq + half*16;
                float4 v = *(const float4*)(Ab + (size_t)(i0 + r)*NN + k0 + kk);
                Ast[kk+0][r] = v.x; Ast[kk+1][r] = v.y;
                Ast[kk+2][r] = v.z; Ast[kk+3][r] = v.w;
            }
        }
        {   // X tile 32 k x 64 e
            int kk = tid >> 4;
            int e4 = (tid & 15) * 4;
            #pragma unroll
            for (int half = 0; half < 2; ++half) {
                int kr = kk + half*16;
                float4 v = *(const float4*)(Xb + (size_t)(k0 + kr)*FE + e4);
                Xs[kr][e4+0] = v.x; Xs[kr][e4+1] = v.y;
                Xs[kr][e4+2] = v.z; Xs[kr][e4+3] = v.w;
            }
        }
        __syncthreads();
        #pragma unroll
        for (int kk = 0; kk < 32; ++kk) {
            float4 a = *(const float4*)&Ast[kk][ty*4];
            float4 x4 = *(const float4*)&Xs[kk][tx*4];
            acc[0][0] = fmaf(a.x, x4.x, acc[0][0]);
            acc[0][1] = fmaf(a.x, x4.y, acc[0][1]);
            acc[0][2] = fmaf(a.x, x4.z, acc[0][2]);
            acc[0][3] = fmaf(a.x, x4.w, acc[0][3]);
            acc[1][0] = fmaf(a.y, x4.x, acc[1][0]);
            acc[1][1] = fmaf(a.y, x4.y, acc[1][1]);
            acc[1][2] = fmaf(a.y, x4.z, acc[1][2]);
            acc[1][3] = fmaf(a.y, x4.w, acc[1][3]);
            acc[2][0] = fmaf(a.z, x4.x, acc[2][0]);
            acc[2][1] = fmaf(a.z, x4.y, acc[2][1]);
            acc[2][2] = fmaf(a.z, x4.z, acc[2][2]);
            acc[2][3] = fmaf(a.z, x4.w, acc[2][3]);
            acc[3][0] = fmaf(a.w, x4.x, acc[3][0]);
            acc[3][1] = fmaf(a.w, x4.y, acc[3][1]);
            acc[3][2] = fmaf(a.w, x4.z, acc[3][2]);
            acc[3][3] = fmaf(a.w, x4.w, acc[3][3]);
        }
        __syncthreads();
    }
    float* P = g_part + (size_t)ks*NB*NN*FE + (size_t)b*NN*FE;
    #pragma unroll
    for (int i = 0; i < 4; ++i) {
        float4 v = make_float4(acc[i][0], acc[i][1], acc[i][2], acc[i][3]);
        *(float4*)(P + (size_t)(i0 + ty*4 + i)*FE + tx*4) = v;
    }
}

// ---------------- K1b: x_emb = relu(partial0 + partial1 + bias) --------------
__global__ void k1b_bias(const float* __restrict__ bias, float* __restrict__ out) {
    int i = blockIdx.x*blockDim.x + threadIdx.x;     // exactly 262144 threads
    float v = g_part[i] + g_part[NB*NN*FE + i] + bias[i & 63];
    out[i] = fmaxf(v, 0.f);
}

// ---------------- K2: centroid = mean over N (per batch, per e) --------------
__global__ void k2_cent(const float* __restrict__ xemb) {
    int be = blockIdx.x;               // 0..127
    int b = be >> 6, e = be & 63;
    const float* p = xemb + (size_t)b*NN*FE + e;
    float s = 0.f;
    for (int n = threadIdx.x; n < NN; n += 256)
        s += p[(size_t)n*FE];
    __shared__ float sm[256];
    sm[threadIdx.x] = s; __syncthreads();
    for (int st = 128; st; st >>= 1) {
        if (threadIdx.x < st) sm[threadIdx.x] += sm[threadIdx.x + st];
        __syncthreads();
    }
    if (threadIdx.x == 0) g_cent[be] = sm[0] * (1.f/NN);
    if (be == 0 && threadIdx.x == 0) g_maxbits = 0u;
}

// ---------------- K3: per-row usq + global max|x-c| --------------------------
__global__ void k3_usq(const float* __restrict__ xemb) {
    int bid = blockIdx.x;              // 0..4095 (b*N + n)
    int b = bid >> 11;
    int e = threadIdx.x;               // 0..63
    float v = xemb[(size_t)bid*FE + e] - g_cent[b*FE + e];
    float sq = v*v, av = fabsf(v);
    #pragma unroll
    for (int o = 16; o; o >>= 1) {
        sq += __shfl_down_sync(0xffffffffu, sq, o);
        av = fmaxf(av, __shfl_down_sync(0xffffffffu, av, o));
    }
    __shared__ float s0[2], s1[2];
    if ((e & 31) == 0) { s0[e>>5] = sq; s1[e>>5] = av; }
    __syncthreads();
    if (e == 0) {
        g_usq[bid] = s0[0] + s0[1];
        atomicMax(&g_maxbits, __float_as_uint(fmaxf(s1[0], s1[1])));
    }
}

// ---------------- K4: edge_index (pure index function), float4 stores --------
__global__ void k4_idx(float* __restrict__ out) {
    long long t = (long long)blockIdx.x*blockDim.x + threadIdx.x;
    const long long total4 = (2LL*BN2) >> 2;
    float4* dst = (float4*)(out + OFF_ROWS);
    long long stride = (long long)gridDim.x * blockDim.x;
    for (; t < total4; t += stride) {
        long long k = t << 2;
        float4 v;
        if (k < BN2) {
            float r = (float)(k >> 11);              // idx // N
            v = make_float4(r, r, r, r);
        } else {
            long long j = k - BN2;
            float base = (float)((j & 2047) + ((j >> 22) << 11));  // col + N*batch
            v = make_float4(base, base+1.f, base+2.f, base+3.f);
        }
        dst[t] = v;
    }
}

// ---------------- K5: Gram + distances + sigmoid weights ---------------------
__global__ void k5_gram(const float* __restrict__ xemb,
                        const float* __restrict__ temp, const float* __restrict__ thr,
                        float* __restrict__ out) {
    __shared__ float Tit[64][68];      // [e][row_i], centered (unscaled)
    __shared__ float Tjt[64][68];      // [e][row_j]
    __shared__ float usqi[64], usqj[64];
    int b = blockIdx.z;
    int i0 = blockIdx.y * 64, j0 = blockIdx.x * 64;
    int tid = threadIdx.x;
    const float* Xb = xemb + (size_t)b*NN*FE;
    {
        int r = tid >> 2;              // 0..63
        int eq = (tid & 3) * 4;
        #pragma unroll
        for (int h = 0; h < 4; ++h) {
            int e = eq + h*16;
            float4 ci = *(const float4*)(&g_cent[b*FE + e]);
            float4 v = *(const float4*)(Xb + (size_t)(i0 + r)*FE + e);
            Tit[e+0][r] = v.x - ci.x; Tit[e+1][r] = v.y - ci.y;
            Tit[e+2][r] = v.z - ci.z; Tit[e+3][r] = v.w - ci.w;
            float4 w = *(const float4*)(Xb + (size_t)(j0 + r)*FE + e);
            Tjt[e+0][r] = w.x - ci.x; Tjt[e+1][r] = w.y - ci.y;
            Tjt[e+2][r] = w.z - ci.z; Tjt[e+3][r] = w.w - ci.w;
        }
    }
    if (tid < 64)       usqi[tid]     = g_usq[b*NN + i0 + tid];
    else if (tid < 128) usqj[tid-64]  = g_usq[b*NN + j0 + (tid-64)];
    __syncthreads();

    int ty = tid >> 4, tx = tid & 15;
    float acc[4][4] = {};
    #pragma unroll
    for (int k = 0; k < 64; ++k) {
        float4 a  = *(const float4*)&Tit[k][ty*4];
        float4 x4 = *(const float4*)&Tjt[k][tx*4];
        acc[0][0] = fmaf(a.x, x4.x, acc[0][0]);
        acc[0][1] = fmaf(a.x, x4.y, acc[0][1]);
        acc[0][2] = fmaf(a.x, x4.z, acc[0][2]);
        acc[0][3] = fmaf(a.x, x4.w, acc[0][3]);
        acc[1][0] = fmaf(a.y, x4.x, acc[1][0]);
        acc[1][1] = fmaf(a.y, x4.y, acc[1][1]);
        acc[1][2] = fmaf(a.y, x4.z, acc[1][2]);
        acc[1][3] = fmaf(a.y, x4.w, acc[1][3]);
        acc[2][0] = fmaf(a.z, x4.x, acc[2][0]);
        acc[2][1] = fmaf(a.z, x4.y, acc[2][1]);
        acc[2][2] = fmaf(a.z, x4.z, acc[2][2]);
        acc[2][3] = fmaf(a.z, x4.w, acc[2][3]);
        acc[3][0] = fmaf(a.w, x4.x, acc[3][0]);
        acc[3][1] = fmaf(a.w, x4.y, acc[3][1]);
        acc[3][2] = fmaf(a.w, x4.z, acc[3][2]);
        acc[3][3] = fmaf(a.w, x4.w, acc[3][3]);
    }
    float mx = __uint_as_float(g_maxbits);
    float s = 0.9f / mx, s2 = s * s;
    float T = *temp, TH = fabsf(*thr);
    float* Ob = out + OFF_WGT + (size_t)b*NN*NN;
    #pragma unroll
    for (int i = 0; i < 4; ++i) {
        float ui = usqi[ty*4 + i];
        float w[4];
        #pragma unroll
        for (int j = 0; j < 4; ++j) {
            float d = s2 * (ui + usqj[tx*4 + j] - 2.f*acc[i][j]);
            d = fmaxf(d, 0.f);
            float z = T * (TH - d);
            w[j] = __fdividef(1.f, 1.f + __expf(-z));
        }
        float4 v = make_float4(w[0], w[1], w[2], w[3]);
        *(float4*)(Ob + (size_t)(i0 + ty*4 + i)*NN + j0 + tx*4) = v;
    }
}

extern "C" void kernel_launch(void* const* d_in, const int* in_sizes, int n_in,
                              void* d_out, int out_size) {
    const float* x    = (const float*)d_in[0];
    const float* A    = (const float*)d_in[1];
    const float* W    = (const float*)d_in[2];
    const float* bias = (const float*)d_in[3];
    const float* temp = (const float*)d_in[4];
    const float* thr  = (const float*)d_in[5];
    float* out = (float*)d_out;

    k0_xw<<<NB*NN/16, 256>>>(x, W);
    k1_gemm<<<dim3(NN/64, 2, NB), 256>>>(A);
    k1b_bias<<<(NB*NN*FE)/256, 256>>>(bias, out);
    k2_cent<<<NB*FE, 256>>>(out);
    k3_usq<<<NB*NN, 64>>>(out);
    k4_idx<<<4096, 256>>>(out);
    k5_gram<<<dim3(NN/64, NN/64, NB), 256>>>(out, temp, thr, out);
}